// round 2
// baseline (speedup 1.0000x reference)
#include <cuda_runtime.h>
#include <cuda_bf16.h>
#include <cstdint>

// ---------------- problem constants ----------------
#define TOKENS 256
#define IN_F   4096
#define OUT_F  14336
#define KC     32
#define NCHUNK (IN_F / KC)        // 128
#define M_TILE 128
#define NTHREADS 512
#define NBLOCKS (OUT_F / M_TILE)  // 112

// ---------------- scratch ----------------
__device__ __nv_bfloat16 g_xhi[TOKENS * IN_F];
__device__ __nv_bfloat16 g_xlo[TOKENS * IN_F];

// ---------------- smem layout ----------------
// per stage: Wbf 128 rows x 64B = 8192 | xhi 256 x 64B = 16384 | xlo 16384
#define STAGE_BYTES 40960
#define SM_W(s)     ((s) * STAGE_BYTES)
#define SM_XHI(s)   (SM_W(s) + 8192)
#define SM_XLO(s)   (SM_W(s) + 24576)
#define SMEM_TOTAL  (2 * STAGE_BYTES)   // 81920 B

// ---------------- helpers ----------------
__device__ __forceinline__ uint32_t smem_u32(const void* p) {
    uint32_t a;
    asm("{ .reg .u64 t; cvta.to.shared.u64 t, %1; cvt.u32.u64 %0, t; }" : "=r"(a) : "l"(p));
    return a;
}

// 64B-row swizzle: XOR bits[5:4] with bits[8:7]
__device__ __forceinline__ uint32_t sw64(uint32_t off) {
    return off ^ ((off >> 3) & 0x30);
}

__device__ __forceinline__ void cp_async16(uint32_t dst, const void* src) {
    asm volatile("cp.async.cg.shared.global [%0], [%1], 16;" :: "r"(dst), "l"(src));
}
#define CP_COMMIT()  asm volatile("cp.async.commit_group;" ::: "memory")
#define CP_WAIT0()   asm volatile("cp.async.wait_group 0;" ::: "memory")

#define LDSM4(R, addr)                                                              \
    asm volatile("ldmatrix.sync.aligned.m8n8.x4.shared.b16 {%0,%1,%2,%3}, [%4];"    \
        : "=r"((R)[0]), "=r"((R)[1]), "=r"((R)[2]), "=r"((R)[3]) : "r"(addr))

#define MMA16816(C, A, B0, B1)                                                      \
    asm volatile("mma.sync.aligned.m16n8k16.row.col.f32.bf16.bf16.f32 "             \
        "{%0,%1,%2,%3}, {%4,%5,%6,%7}, {%8,%9}, {%0,%1,%2,%3};"                     \
        : "+f"((C)[0]), "+f"((C)[1]), "+f"((C)[2]), "+f"((C)[3])                    \
        : "r"((A)[0]), "r"((A)[1]), "r"((A)[2]), "r"((A)[3]), "r"(B0), "r"(B1))

// ---------------- prep: split x into bf16 hi/lo ----------------
__global__ void prep_split_kernel(const float* __restrict__ x) {
    int i = blockIdx.x * blockDim.x + threadIdx.x;
    float v = x[i];
    __nv_bfloat16 h = __float2bfloat16(v);
    float r = v - __bfloat162float(h);
    g_xhi[i] = h;
    g_xlo[i] = __float2bfloat16(r);
}

// ---------------- main GEMM kernel ----------------
__global__ void __launch_bounds__(NTHREADS, 1)
qlinear_kernel(const int* __restrict__ qw, const float* __restrict__ scale,
               const float* __restrict__ bias, float* __restrict__ out) {
    extern __shared__ char smem[];
    const uint32_t sb = smem_u32(smem);
    const int tid  = threadIdx.x;
    const int lane = tid & 31;
    const int wid  = tid >> 5;
    const int wm   = wid & 3;   // 4 warps along M (32 rows each)
    const int wn   = wid >> 2;  // 4 warps along N (64 tokens each)
    const int out0 = blockIdx.x * M_TILE;

    // ---- W loader setup: thread t handles row t/4, ints [q*8, q*8+8) of chunk ----
    const int wrow = tid >> 2;      // 0..127
    const int wq   = tid & 3;
    const int4* wptr = (const int4*)(qw + (size_t)(out0 + wrow) * IN_F + wq * 8);
    const uint32_t w_sts_off = sw64((uint32_t)wrow * 64 + (uint32_t)wq * 16);

    // ---- x cp.async setup: 2 x 16B units per buffer per thread ----
    const char* xhi_b = (const char*)g_xhi;
    const char* xlo_b = (const char*)g_xlo;

    // ---- ldmatrix base indices ----
    const int aRow = wm * 32 + (lane & 15);
    const int aKs  = (lane & 16) ? 16 : 0;
    const int bRow = wn * 64 + (lane & 7) + ((lane & 16) ? 8 : 0);
    const int bKs  = (lane & 8) ? 16 : 0;

    float acc[2][8][4];
    #pragma unroll
    for (int i = 0; i < 2; i++)
        #pragma unroll
        for (int j = 0; j < 8; j++)
            #pragma unroll
            for (int k = 0; k < 4; k++) acc[i][j][k] = 0.0f;

    // ---- prologue: x chunk0 -> stage0, W chunk0 -> regs ----
    {
        #pragma unroll
        for (int j = 0; j < 2; j++) {
            int u = tid + j * NTHREADS;          // 0..1023
            int row = u >> 2, c = u & 3;
            uint32_t d = sw64((uint32_t)row * 64 + (uint32_t)c * 16);
            size_t so = (size_t)row * (IN_F * 2) + (size_t)c * 16;
            cp_async16(sb + SM_XHI(0) + d, xhi_b + so);
            cp_async16(sb + SM_XLO(0) + d, xlo_b + so);
        }
        CP_COMMIT();
    }
    int4 v0 = wptr[0];
    int4 v1 = wptr[1];

    for (int i = 0; i < NCHUNK; i++) {
        const int s = i & 1;
        const uint32_t sw_base  = sb + SM_W(s);
        const uint32_t shi_base = sb + SM_XHI(s);
        const uint32_t slo_base = sb + SM_XLO(s);

        // 1. convert + STS W chunk i
        {
            __nv_bfloat162 h0, h1, h2, h3;
            h0.x = __float2bfloat16((float)v0.x); h0.y = __float2bfloat16((float)v0.y);
            h1.x = __float2bfloat16((float)v0.z); h1.y = __float2bfloat16((float)v0.w);
            h2.x = __float2bfloat16((float)v1.x); h2.y = __float2bfloat16((float)v1.y);
            h3.x = __float2bfloat16((float)v1.z); h3.y = __float2bfloat16((float)v1.w);
            uint32_t p0 = *(uint32_t*)&h0, p1 = *(uint32_t*)&h1;
            uint32_t p2 = *(uint32_t*)&h2, p3 = *(uint32_t*)&h3;
            asm volatile("st.shared.v4.b32 [%0], {%1,%2,%3,%4};"
                         :: "r"(sw_base + w_sts_off), "r"(p0), "r"(p1), "r"(p2), "r"(p3)
                         : "memory");
        }

        // 2. wait x chunk i, make stage visible to all
        CP_WAIT0();
        __syncthreads();

        // 3. prefetch chunk i+1 into the other stage
        if (i + 1 < NCHUNK) {
            const int sn = s ^ 1;
            const size_t co = (size_t)(i + 1) * (KC * 2);  // byte offset along K
            #pragma unroll
            for (int j = 0; j < 2; j++) {
                int u = tid + j * NTHREADS;
                int row = u >> 2, c = u & 3;
                uint32_t d = sw64((uint32_t)row * 64 + (uint32_t)c * 16);
                size_t so = (size_t)row * (IN_F * 2) + co + (size_t)c * 16;
                cp_async16(sb + SM_XHI(sn) + d, xhi_b + so);
                cp_async16(sb + SM_XLO(sn) + d, xlo_b + so);
            }
            CP_COMMIT();
            v0 = wptr[(i + 1) * 8];
            v1 = wptr[(i + 1) * 8 + 1];
        }

        // 4. compute chunk i: 2 k16 steps, hi + lo GEMMs into same acc
        #pragma unroll
        for (int ks = 0; ks < 2; ks++) {
            const uint32_t kb = (uint32_t)ks * 32;
            uint32_t a[2][4];
            #pragma unroll
            for (int fm = 0; fm < 2; fm++)
                LDSM4(a[fm], sw_base + sw64((uint32_t)(aRow + fm * 16) * 64 + kb + aKs));

            uint32_t b[4][4];
            #pragma unroll
            for (int fn = 0; fn < 4; fn++)
                LDSM4(b[fn], shi_base + sw64((uint32_t)(bRow + fn * 16) * 64 + kb + bKs));
            #pragma unroll
            for (int fm = 0; fm < 2; fm++)
                #pragma unroll
                for (int fn = 0; fn < 4; fn++) {
                    MMA16816(acc[fm][2 * fn],     a[fm], b[fn][0], b[fn][1]);
                    MMA16816(acc[fm][2 * fn + 1], a[fm], b[fn][2], b[fn][3]);
                }

            #pragma unroll
            for (int fn = 0; fn < 4; fn++)
                LDSM4(b[fn], slo_base + sw64((uint32_t)(bRow + fn * 16) * 64 + kb + bKs));
            #pragma unroll
            for (int fm = 0; fm < 2; fm++)
                #pragma unroll
                for (int fn = 0; fn < 4; fn++) {
                    MMA16816(acc[fm][2 * fn],     a[fm], b[fn][0], b[fn][1]);
                    MMA16816(acc[fm][2 * fn + 1], a[fm], b[fn][2], b[fn][3]);
                }
        }
    }

    // ---- epilogue: fuse scale + bias, write f32 ----
    const int m_base = out0 + wm * 32 + (lane >> 2);
    #pragma unroll
    for (int fm = 0; fm < 2; fm++) {
        const int m0 = m_base + fm * 16;
        const float s0 = scale[m0],     bi0 = bias[m0];
        const float s1 = scale[m0 + 8], bi1 = bias[m0 + 8];
        #pragma unroll
        for (int nf = 0; nf < 8; nf++) {
            const int t0 = wn * 64 + nf * 8 + (lane & 3) * 2;
            float* o = out + (size_t)t0 * OUT_F;
            o[m0]             = fmaf(acc[fm][nf][0], s0, bi0);
            o[OUT_F + m0]     = fmaf(acc[fm][nf][1], s0, bi0);
            o[m0 + 8]         = fmaf(acc[fm][nf][2], s1, bi1);
            o[OUT_F + m0 + 8] = fmaf(acc[fm][nf][3], s1, bi1);
        }
    }
}

// ---------------- launch ----------------
extern "C" void kernel_launch(void* const* d_in, const int* in_sizes, int n_in,
                              void* d_out, int out_size) {
    const float* x     = (const float*)d_in[0];
    const int*   qw    = (const int*)d_in[1];
    const float* scale = (const float*)d_in[2];
    const float* bias  = (const float*)d_in[3];
    float* out = (float*)d_out;

    prep_split_kernel<<<(TOKENS * IN_F) / 256, 256>>>(x);

    cudaFuncSetAttribute(qlinear_kernel, cudaFuncAttributeMaxDynamicSharedMemorySize, SMEM_TOTAL);
    qlinear_kernel<<<NBLOCKS, NTHREADS, SMEM_TOTAL>>>(qw, scale, bias, out);
}

// round 3
// speedup vs baseline: 1.3225x; 1.3225x over previous
#include <cuda_runtime.h>
#include <cuda_fp16.h>
#include <cstdint>

// ---------------- problem constants ----------------
#define TOKENS 256
#define IN_F   4096
#define OUT_F  14336
#define KC     64
#define NCHUNK (IN_F / KC)        // 64
#define M_TILE 128
#define NTHREADS 512
#define NBLOCKS (OUT_F / M_TILE)  // 112

// ---------------- scratch ----------------
__device__ __half g_xh[TOKENS * IN_F];

// ---------------- smem layout ----------------
// per stage (128B rows): W 128x128B = 16384 | x 256x128B = 32768
#define STAGE_BYTES 49152
#define SM_W(s)     ((s) * STAGE_BYTES)
#define SM_X(s)     (SM_W(s) + 16384)
#define SMEM_TOTAL  (2 * STAGE_BYTES)   // 98304 B

// ---------------- helpers ----------------
__device__ __forceinline__ uint32_t smem_u32(const void* p) {
    uint32_t a;
    asm("{ .reg .u64 t; cvta.to.shared.u64 t, %1; cvt.u32.u64 %0, t; }" : "=r"(a) : "l"(p));
    return a;
}

// 128B-row swizzle: XOR bits[6:4] with bits[9:7]
__device__ __forceinline__ uint32_t sw128(uint32_t off) {
    return off ^ ((off >> 3) & 0x70);
}

__device__ __forceinline__ void cp_async16(uint32_t dst, const void* src) {
    asm volatile("cp.async.cg.shared.global [%0], [%1], 16;" :: "r"(dst), "l"(src));
}
#define CP_COMMIT()  asm volatile("cp.async.commit_group;" ::: "memory")
#define CP_WAIT0()   asm volatile("cp.async.wait_group 0;" ::: "memory")

#define LDSM4(R, addr)                                                              \
    asm volatile("ldmatrix.sync.aligned.m8n8.x4.shared.b16 {%0,%1,%2,%3}, [%4];"    \
        : "=r"((R)[0]), "=r"((R)[1]), "=r"((R)[2]), "=r"((R)[3]) : "r"(addr))

#define MMA16816(C, A, B0, B1)                                                      \
    asm volatile("mma.sync.aligned.m16n8k16.row.col.f32.f16.f16.f32 "               \
        "{%0,%1,%2,%3}, {%4,%5,%6,%7}, {%8,%9}, {%0,%1,%2,%3};"                     \
        : "+f"((C)[0]), "+f"((C)[1]), "+f"((C)[2]), "+f"((C)[3])                    \
        : "r"((A)[0]), "r"((A)[1]), "r"((A)[2]), "r"((A)[3]), "r"(B0), "r"(B1))

// ---------------- prep: x -> fp16 ----------------
__global__ void prep_half_kernel(const float* __restrict__ x) {
    int i = blockIdx.x * blockDim.x + threadIdx.x;
    float2 v = ((const float2*)x)[i];
    __half2 h;
    h.x = __float2half_rn(v.x);
    h.y = __float2half_rn(v.y);
    ((__half2*)g_xh)[i] = h;
}

// ---------------- main GEMM kernel ----------------
__global__ void __launch_bounds__(NTHREADS, 1)
qlinear_kernel(const int* __restrict__ qw, const float* __restrict__ scale,
               const float* __restrict__ bias, float* __restrict__ out) {
    extern __shared__ char smem[];
    const uint32_t sb = smem_u32(smem);
    const int tid  = threadIdx.x;
    const int lane = tid & 31;
    const int wid  = tid >> 5;
    const int wm   = wid & 3;   // 4 warps along M (32 rows each)
    const int wn   = wid >> 2;  // 4 warps along N (64 tokens each)
    const int out0 = blockIdx.x * M_TILE;

    // ---- W loader: thread t -> row t/4, ints [16q, 16q+16) of each chunk ----
    const int wrow = tid >> 2;      // 0..127
    const int wq   = tid & 3;
    const int4* wptr = (const int4*)(qw + (size_t)(out0 + wrow) * IN_F + wq * 16);
    const uint32_t w_sts0 = sw128((uint32_t)wrow * 128 + (uint32_t)wq * 32);
    const uint32_t w_sts1 = sw128((uint32_t)wrow * 128 + (uint32_t)wq * 32 + 16);

    const char* xh_b = (const char*)g_xh;

    // ---- ldmatrix base indices ----
    const int aRow = wm * 32 + (lane & 15);
    const int aKs  = (lane & 16) ? 16 : 0;
    const int bRow = wn * 64 + (lane & 7) + ((lane & 16) ? 8 : 0);
    const int bKs  = (lane & 8) ? 16 : 0;

    float acc[2][8][4];
    #pragma unroll
    for (int i = 0; i < 2; i++)
        #pragma unroll
        for (int j = 0; j < 8; j++)
            #pragma unroll
            for (int k = 0; k < 4; k++) acc[i][j][k] = 0.0f;

    // ---- prologue: x chunk0 -> stage0, W chunk0 -> regs ----
    {
        #pragma unroll
        for (int j = 0; j < 4; j++) {
            int u = tid + j * NTHREADS;          // 0..2047
            int row = u >> 3, c = u & 7;
            uint32_t d = sw128((uint32_t)row * 128 + (uint32_t)c * 16);
            size_t so = (size_t)row * (IN_F * 2) + (size_t)c * 16;
            cp_async16(sb + SM_X(0) + d, xh_b + so);
        }
        CP_COMMIT();
    }
    int4 v0 = wptr[0], v1 = wptr[1], v2 = wptr[2], v3 = wptr[3];

    for (int i = 0; i < NCHUNK; i++) {
        const int s = i & 1;
        const uint32_t sw_base = sb + SM_W(s);
        const uint32_t sx_base = sb + SM_X(s);

        // 1. convert + STS W chunk i (16 ints -> 16 halves)
        {
            __half2 h[8];
            h[0] = __halves2half2(__int2half_rn(v0.x), __int2half_rn(v0.y));
            h[1] = __halves2half2(__int2half_rn(v0.z), __int2half_rn(v0.w));
            h[2] = __halves2half2(__int2half_rn(v1.x), __int2half_rn(v1.y));
            h[3] = __halves2half2(__int2half_rn(v1.z), __int2half_rn(v1.w));
            h[4] = __halves2half2(__int2half_rn(v2.x), __int2half_rn(v2.y));
            h[5] = __halves2half2(__int2half_rn(v2.z), __int2half_rn(v2.w));
            h[6] = __halves2half2(__int2half_rn(v3.x), __int2half_rn(v3.y));
            h[7] = __halves2half2(__int2half_rn(v3.z), __int2half_rn(v3.w));
            uint32_t* p = (uint32_t*)h;
            asm volatile("st.shared.v4.b32 [%0], {%1,%2,%3,%4};"
                         :: "r"(sw_base + w_sts0), "r"(p[0]), "r"(p[1]), "r"(p[2]), "r"(p[3]) : "memory");
            asm volatile("st.shared.v4.b32 [%0], {%1,%2,%3,%4};"
                         :: "r"(sw_base + w_sts1), "r"(p[4]), "r"(p[5]), "r"(p[6]), "r"(p[7]) : "memory");
        }

        // 2. wait x chunk i, make stage visible
        CP_WAIT0();
        __syncthreads();

        // 3. prefetch chunk i+1
        if (i + 1 < NCHUNK) {
            const int sn = s ^ 1;
            const size_t co = (size_t)(i + 1) * (KC * 2);
            #pragma unroll
            for (int j = 0; j < 4; j++) {
                int u = tid + j * NTHREADS;
                int row = u >> 3, c = u & 7;
                uint32_t d = sw128((uint32_t)row * 128 + (uint32_t)c * 16);
                size_t so = (size_t)row * (IN_F * 2) + co + (size_t)c * 16;
                cp_async16(sb + SM_X(sn) + d, xh_b + so);
            }
            CP_COMMIT();
            const int4* wnp = wptr + (size_t)(i + 1) * 16;
            v0 = wnp[0]; v1 = wnp[1]; v2 = wnp[2]; v3 = wnp[3];
        }

        // 4. compute chunk i: 4 k16 steps
        #pragma unroll
        for (int ks = 0; ks < 4; ks++) {
            const uint32_t kb = (uint32_t)ks * 32;
            uint32_t a[2][4];
            #pragma unroll
            for (int fm = 0; fm < 2; fm++)
                LDSM4(a[fm], sw_base + sw128((uint32_t)(aRow + fm * 16) * 128 + kb + aKs));

            uint32_t b[4][4];
            #pragma unroll
            for (int fn = 0; fn < 4; fn++)
                LDSM4(b[fn], sx_base + sw128((uint32_t)(bRow + fn * 16) * 128 + kb + bKs));
            #pragma unroll
            for (int fm = 0; fm < 2; fm++)
                #pragma unroll
                for (int fn = 0; fn < 4; fn++) {
                    MMA16816(acc[fm][2 * fn],     a[fm], b[fn][0], b[fn][1]);
                    MMA16816(acc[fm][2 * fn + 1], a[fm], b[fn][2], b[fn][3]);
                }
        }
    }

    // ---- epilogue: fuse scale + bias ----
    const int m_base = out0 + wm * 32 + (lane >> 2);
    #pragma unroll
    for (int fm = 0; fm < 2; fm++) {
        const int m0 = m_base + fm * 16;
        const float s0 = scale[m0],     bi0 = bias[m0];
        const float s1 = scale[m0 + 8], bi1 = bias[m0 + 8];
        #pragma unroll
        for (int nf = 0; nf < 8; nf++) {
            const int t0 = wn * 64 + nf * 8 + (lane & 3) * 2;
            float* o = out + (size_t)t0 * OUT_F;
            o[m0]             = fmaf(acc[fm][nf][0], s0, bi0);
            o[OUT_F + m0]     = fmaf(acc[fm][nf][1], s0, bi0);
            o[m0 + 8]         = fmaf(acc[fm][nf][2], s1, bi1);
            o[OUT_F + m0 + 8] = fmaf(acc[fm][nf][3], s1, bi1);
        }
    }
}

// ---------------- launch ----------------
extern "C" void kernel_launch(void* const* d_in, const int* in_sizes, int n_in,
                              void* d_out, int out_size) {
    const float* x     = (const float*)d_in[0];
    const int*   qw    = (const int*)d_in[1];
    const float* scale = (const float*)d_in[2];
    const float* bias  = (const float*)d_in[3];
    float* out = (float*)d_out;

    prep_half_kernel<<<(TOKENS * IN_F / 2) / 256, 256>>>(x);

    cudaFuncSetAttribute(qlinear_kernel, cudaFuncAttributeMaxDynamicSharedMemorySize, SMEM_TOTAL);
    qlinear_kernel<<<NBLOCKS, NTHREADS, SMEM_TOTAL>>>(qw, scale, bias, out);
}